// round 2
// baseline (speedup 1.0000x reference)
#include <cuda_runtime.h>
#include <cstddef>

// ---------------------------------------------------------------------------
// Problem dims (fixed): B=4, T=2048, C=2048, H=16, HD=128
// ---------------------------------------------------------------------------
#define B_  4
#define T_  2048
#define C_  2048
#define BT_ (B_ * T_)          // 8192
#define C3_ (3 * C_)           // 6144
#define C4_ (4 * C_)           // 8192
#define NH_ 16
#define HD_ 128

// ---------------------------------------------------------------------------
// Scratch (device globals: allocation-free rule)
// ---------------------------------------------------------------------------
__device__ float g_h[(size_t)BT_ * C_];      // LN output (reused for LN1/LN2)
__device__ float g_qkv[(size_t)BT_ * C3_];   // QKV
__device__ float g_y[(size_t)BT_ * C_];      // attention output
__device__ float g_fc[(size_t)BT_ * C4_];    // gelu(fc) activations

// ---------------------------------------------------------------------------
// LayerNorm: one block per row of 2048
// ---------------------------------------------------------------------------
__global__ __launch_bounds__(256) void ln_k(const float* __restrict__ x,
                                            const float* __restrict__ g,
                                            const float* __restrict__ b,
                                            float* __restrict__ out)
{
    size_t row = blockIdx.x;
    const float4* xr = (const float4*)(x + row * (size_t)C_);
    int tid = threadIdx.x;
    float4 v0 = xr[tid];
    float4 v1 = xr[tid + 256];
    float s  = v0.x + v0.y + v0.z + v0.w + v1.x + v1.y + v1.z + v1.w;
    float s2 = v0.x*v0.x + v0.y*v0.y + v0.z*v0.z + v0.w*v0.w
             + v1.x*v1.x + v1.y*v1.y + v1.z*v1.z + v1.w*v1.w;
    #pragma unroll
    for (int o = 16; o > 0; o >>= 1) {
        s  += __shfl_xor_sync(0xffffffffu, s,  o);
        s2 += __shfl_xor_sync(0xffffffffu, s2, o);
    }
    __shared__ float ssum[8], ssq[8];
    __shared__ float mu_s, inv_s;
    int wid = tid >> 5, lane = tid & 31;
    if (lane == 0) { ssum[wid] = s; ssq[wid] = s2; }
    __syncthreads();
    if (tid == 0) {
        float S = 0.f, S2 = 0.f;
        #pragma unroll
        for (int i = 0; i < 8; ++i) { S += ssum[i]; S2 += ssq[i]; }
        float mu  = S * (1.f / (float)C_);
        float var = S2 * (1.f / (float)C_) - mu * mu;
        mu_s  = mu;
        inv_s = rsqrtf(var + 1e-5f);
    }
    __syncthreads();
    float mu = mu_s, inv = inv_s;
    const float4* g4 = (const float4*)g;
    const float4* b4 = (const float4*)b;
    float4* o4 = (float4*)(out + row * (size_t)C_);
    {
        float4 gg = g4[tid], bb = b4[tid], r;
        r.x = (v0.x - mu) * inv * gg.x + bb.x;
        r.y = (v0.y - mu) * inv * gg.y + bb.y;
        r.z = (v0.z - mu) * inv * gg.z + bb.z;
        r.w = (v0.w - mu) * inv * gg.w + bb.w;
        o4[tid] = r;
    }
    {
        float4 gg = g4[tid + 256], bb = b4[tid + 256], r;
        r.x = (v1.x - mu) * inv * gg.x + bb.x;
        r.y = (v1.y - mu) * inv * gg.y + bb.y;
        r.z = (v1.z - mu) * inv * gg.z + bb.z;
        r.w = (v1.w - mu) * inv * gg.w + bb.w;
        o4[tid + 256] = r;
    }
}

// ---------------------------------------------------------------------------
// SGEMM: C[M,N] = A[M,K] @ B[K,N] + bias (+gelu | +residual)
// 128x128 block tile, K-tile 8, 256 threads, 8x8 per thread (split quadrants)
// Register-prefetch of the next K-tile overlaps LDG with the FFMA block.
// ---------------------------------------------------------------------------
#define EPI_NONE 0
#define EPI_GELU 1
#define EPI_RES  2

__device__ __forceinline__ float fast_gelu(float v)
{
    float z = 0.79788456080286536f * (v + 0.044715f * v * v * v);
    float e = __expf(2.f * z);
    float th = 1.f - 2.f / (e + 1.f);    // tanh(z), safe at +-inf
    return 0.5f * v * (1.f + th);
}

template<int EPI>
__global__ __launch_bounds__(256) void sgemm_k(
    int M, int N, int K,
    const float* __restrict__ A, const float* __restrict__ B,
    const float* __restrict__ bias, const float* __restrict__ R,
    float* __restrict__ C)
{
    __shared__ float As[8][128];
    __shared__ float Bs[8][128];
    int tid = threadIdx.x;
    int rowBase = blockIdx.y * 128;
    int colBase = blockIdx.x * 128;
    int aRow = tid >> 1, aCol = (tid & 1) << 2;
    int bRow = tid >> 5, bCol = (tid & 31) << 2;
    const float* Ap = A + (size_t)(rowBase + aRow) * K + aCol;
    const float* Bp = B + (size_t)bRow * N + colBase + bCol;
    int ty = tid >> 4, tx = tid & 15;

    float acc[8][8];
    #pragma unroll
    for (int i = 0; i < 8; ++i)
        #pragma unroll
        for (int j = 0; j < 8; ++j) acc[i][j] = 0.f;

    int nk = K >> 3;
    float4 av = *(const float4*)Ap;
    float4 bv = *(const float4*)Bp;
    for (int t = 0; t < nk; ++t) {
        As[aCol + 0][aRow] = av.x;
        As[aCol + 1][aRow] = av.y;
        As[aCol + 2][aRow] = av.z;
        As[aCol + 3][aRow] = av.w;
        *(float4*)&Bs[bRow][bCol] = bv;
        __syncthreads();
        Ap += 8;
        Bp += (size_t)8 * N;
        if (t + 1 < nk) {            // prefetch next tile during compute
            av = *(const float4*)Ap;
            bv = *(const float4*)Bp;
        }
        #pragma unroll
        for (int kk = 0; kk < 8; ++kk) {
            float4 a0 = *(const float4*)&As[kk][ty * 4];
            float4 a1 = *(const float4*)&As[kk][64 + ty * 4];
            float4 b0 = *(const float4*)&Bs[kk][tx * 4];
            float4 b1 = *(const float4*)&Bs[kk][64 + tx * 4];
            float a[8] = {a0.x, a0.y, a0.z, a0.w, a1.x, a1.y, a1.z, a1.w};
            float bb[8] = {b0.x, b0.y, b0.z, b0.w, b1.x, b1.y, b1.z, b1.w};
            #pragma unroll
            for (int i = 0; i < 8; ++i)
                #pragma unroll
                for (int j = 0; j < 8; ++j)
                    acc[i][j] += a[i] * bb[j];
        }
        __syncthreads();
    }

    #pragma unroll
    for (int ii = 0; ii < 8; ++ii) {
        int r = rowBase + ((ii < 4) ? (ty * 4 + ii) : (64 + ty * 4 + ii - 4));
        #pragma unroll
        for (int jh = 0; jh < 2; ++jh) {
            int c = colBase + jh * 64 + tx * 4;
            float vals[4];
            #pragma unroll
            for (int u = 0; u < 4; ++u) {
                float v = acc[ii][jh * 4 + u] + bias[c + u];
                if (EPI == EPI_GELU) v = fast_gelu(v);
                vals[u] = v;
            }
            if (EPI == EPI_RES) {
                float4 rv = *(const float4*)(R + (size_t)r * N + c);
                vals[0] += rv.x; vals[1] += rv.y; vals[2] += rv.z; vals[3] += rv.w;
            }
            *(float4*)(C + (size_t)r * N + c) =
                make_float4(vals[0], vals[1], vals[2], vals[3]);
        }
    }
}

// ---------------------------------------------------------------------------
// Causal flash attention. Grid: (qtile=32, bh=64). Block: 128 threads.
// Thread t owns q-row (t>>1) of the 64-row tile and d-half (t&1)*64.
// K/V tiles of 64 rows staged in dynamic smem; online softmax.
// ---------------------------------------------------------------------------
#define ATTN_SMEM ((64 * 132 + 2 * 64 * 128) * 4)

__global__ __launch_bounds__(128) void attn_k(const float* __restrict__ qkv,
                                              float* __restrict__ y)
{
    extern __shared__ float sm[];
    float (*qs)[132] = (float(*)[132])sm;
    float (*ks)[128] = (float(*)[128])(sm + 64 * 132);
    float (*vs)[128] = (float(*)[128])(sm + 64 * 132 + 64 * 128);

    int qt = blockIdx.x;            // 0..31
    int bh = blockIdx.y;            // 0..63
    int b  = bh >> 4;
    int h  = bh & 15;
    int tid = threadIdx.x;
    int r    = tid >> 1;            // q row in tile
    int col0 = (tid & 1) * 64;      // d-half
    const float scale = 0.08838834764831845f;   // 1/sqrt(128)

    const float* base = qkv + (size_t)b * T_ * C3_ + (size_t)h * HD_;
    int q0 = qt * 64;

    // load Q tile (coalesced float4)
    for (int i = tid; i < 64 * 32; i += 128) {
        int rr = i >> 5, c4 = (i & 31) << 2;
        *(float4*)&qs[rr][c4] =
            *(const float4*)(base + (size_t)(q0 + rr) * C3_ + c4);
    }

    float o[64];
    #pragma unroll
    for (int d = 0; d < 64; ++d) o[d] = 0.f;
    float m = -1e30f, l = 0.f;

    for (int kt = 0; kt <= qt; ++kt) {
        int k0 = kt * 64;
        __syncthreads();   // prior-tile readers done (also covers Q load on iter 0)
        for (int i = tid; i < 64 * 32; i += 128) {
            int rr = i >> 5, c4 = (i & 31) << 2;
            *(float4*)&ks[rr][c4] =
                *(const float4*)(base + C_ + (size_t)(k0 + rr) * C3_ + c4);
            *(float4*)&vs[rr][c4] =
                *(const float4*)(base + 2 * C_ + (size_t)(k0 + rr) * C3_ + c4);
        }
        __syncthreads();

        #pragma unroll 1
        for (int sub = 0; sub < 2; ++sub) {
            int j0 = sub * 32;
            float s[32];
            #pragma unroll
            for (int j = 0; j < 32; ++j) s[j] = 0.f;

            // S = Q . K^T over this thread's 64-dim half, 16-dim chunks
            #pragma unroll 1
            for (int c = 0; c < 64; c += 16) {
                float qr[16];
                #pragma unroll
                for (int u = 0; u < 16; u += 4)
                    *(float4*)&qr[u] = *(float4*)&qs[r][col0 + c + u];
                #pragma unroll
                for (int j = 0; j < 32; ++j) {
                    const float* kr = &ks[j0 + j][col0 + c];
                    float4 k1 = *(const float4*)(kr);
                    float4 k2 = *(const float4*)(kr + 4);
                    float4 k3 = *(const float4*)(kr + 8);
                    float4 k4 = *(const float4*)(kr + 12);
                    s[j] += qr[0]  * k1.x + qr[1]  * k1.y + qr[2]  * k1.z + qr[3]  * k1.w
                          + qr[4]  * k2.x + qr[5]  * k2.y + qr[6]  * k2.z + qr[7]  * k2.w
                          + qr[8]  * k3.x + qr[9]  * k3.y + qr[10] * k3.z + qr[11] * k3.w
                          + qr[12] * k4.x + qr[13] * k4.y + qr[14] * k4.z + qr[15] * k4.w;
                }
            }
            // combine the two d-halves (lane pairs 2i, 2i+1)
            #pragma unroll
            for (int j = 0; j < 32; ++j)
                s[j] = scale * (s[j] + __shfl_xor_sync(0xffffffffu, s[j], 1));

            if (kt == qt) {
                #pragma unroll
                for (int j = 0; j < 32; ++j)
                    if (j0 + j > r) s[j] = -1e30f;
            }

            float mnew = m;
            #pragma unroll
            for (int j = 0; j < 32; ++j) mnew = fmaxf(mnew, s[j]);
            float corr = __expf(m - mnew);
            l *= corr;
            #pragma unroll
            for (int d = 0; d < 64; ++d) o[d] *= corr;
            float ls = 0.f;
            #pragma unroll
            for (int j = 0; j < 32; ++j) {
                float p = __expf(s[j] - mnew);
                s[j] = p;
                ls += p;
            }
            l += ls;
            m = mnew;

            // O += P . V  (V broadcast from smem)
            #pragma unroll
            for (int j = 0; j < 32; ++j) {
                float pj = s[j];
                const float* vr = &vs[j0 + j][col0];
                #pragma unroll
                for (int d = 0; d < 64; d += 4) {
                    float4 vv = *(const float4*)(vr + d);
                    o[d]     += pj * vv.x;
                    o[d + 1] += pj * vv.y;
                    o[d + 2] += pj * vv.z;
                    o[d + 3] += pj * vv.w;
                }
            }
        }
    }

    float inv = 1.f / l;
    float* yr = y + (size_t)(b * T_ + q0 + r) * C_ + h * HD_ + col0;
    #pragma unroll
    for (int d = 0; d < 64; d += 4) {
        *(float4*)(yr + d) = make_float4(o[d] * inv, o[d + 1] * inv,
                                         o[d + 2] * inv, o[d + 3] * inv);
    }
}

// ---------------------------------------------------------------------------
// Launch
// ---------------------------------------------------------------------------
extern "C" void kernel_launch(void* const* d_in, const int* in_sizes, int n_in,
                              void* d_out, int out_size)
{
    const float* x         = (const float*)d_in[0];
    const float* ln1_g     = (const float*)d_in[1];
    const float* ln1_b     = (const float*)d_in[2];
    const float* w_attn    = (const float*)d_in[3];
    const float* b_attn    = (const float*)d_in[4];
    const float* w_proj    = (const float*)d_in[5];
    const float* b_proj    = (const float*)d_in[6];
    const float* ln2_g     = (const float*)d_in[7];
    const float* ln2_b     = (const float*)d_in[8];
    const float* w_fc      = (const float*)d_in[9];
    const float* b_fc      = (const float*)d_in[10];
    const float* w_fc_proj = (const float*)d_in[11];
    const float* b_fc_proj = (const float*)d_in[12];
    float* out = (float*)d_out;

    float *h, *qkv, *y, *fc;
    cudaGetSymbolAddress((void**)&h,   g_h);
    cudaGetSymbolAddress((void**)&qkv, g_qkv);
    cudaGetSymbolAddress((void**)&y,   g_y);
    cudaGetSymbolAddress((void**)&fc,  g_fc);

    cudaFuncSetAttribute(attn_k, cudaFuncAttributeMaxDynamicSharedMemorySize,
                         ATTN_SMEM);

    // 1) h = LN1(x)
    ln_k<<<BT_, 256>>>(x, ln1_g, ln1_b, h);
    // 2) qkv = h @ w_attn + b_attn
    sgemm_k<EPI_NONE><<<dim3(C3_ / 128, BT_ / 128), 256>>>(
        BT_, C3_, C_, h, w_attn, b_attn, nullptr, qkv);
    // 3) y = causal_attention(qkv)
    attn_k<<<dim3(T_ / 64, B_ * NH_), 128, ATTN_SMEM>>>(qkv, y);
    // 4) out = x + y @ w_proj + b_proj
    sgemm_k<EPI_RES><<<dim3(C_ / 128, BT_ / 128), 256>>>(
        BT_, C_, C_, y, w_proj, b_proj, x, out);
    // 5) h = LN2(out)
    ln_k<<<BT_, 256>>>(out, ln2_g, ln2_b, h);
    // 6) fc = gelu(h @ w_fc + b_fc)
    sgemm_k<EPI_GELU><<<dim3(C4_ / 128, BT_ / 128), 256>>>(
        BT_, C4_, C_, h, w_fc, b_fc, nullptr, fc);
    // 7) out = out + fc @ w_fc_proj + b_fc_proj
    sgemm_k<EPI_RES><<<dim3(C_ / 128, BT_ / 128), 256>>>(
        BT_, C_, C4_, fc, w_fc_proj, b_fc_proj, out, out);
}

// round 7
// speedup vs baseline: 1.7054x; 1.7054x over previous
#include <cuda_runtime.h>
#include <cstdint>
#include <cstddef>

// ---------------------------------------------------------------------------
// Problem dims (fixed): B=4, T=2048, C=2048, H=16, HD=128
// ---------------------------------------------------------------------------
#define B_  4
#define T_  2048
#define C_  2048
#define BT_ (B_ * T_)          // 8192
#define C3_ (3 * C_)           // 6144
#define C4_ (4 * C_)           // 8192
#define NH_ 16
#define HD_ 128

// ---------------------------------------------------------------------------
// Scratch (device globals: allocation-free rule)
// ---------------------------------------------------------------------------
__device__ float g_h[(size_t)BT_ * C_];       // LN output
__device__ float g_qkv[(size_t)BT_ * C3_];    // QKV
__device__ float g_y[(size_t)BT_ * C_];       // attention output
__device__ float g_fc[(size_t)BT_ * C4_];     // gelu(fc)
__device__ float g_wt_attn[(size_t)C3_ * C_];    // w_attn^T   [6144,2048]
__device__ float g_wt_proj[(size_t)C_ * C_];     // w_proj^T   [2048,2048]
__device__ float g_wt_fc[(size_t)C4_ * C_];      // w_fc^T     [8192,2048]
__device__ float g_wt_fcproj[(size_t)C_ * C4_];  // w_fc_proj^T[2048,8192]

// ---------------------------------------------------------------------------
// Weight transpose: in[R][Cc] -> out[Cc][R]   (dims multiples of 32)
// ---------------------------------------------------------------------------
__global__ __launch_bounds__(256) void transpose_k(const float* __restrict__ in,
                                                   float* __restrict__ out,
                                                   int R, int Cc)
{
    __shared__ float t[32][33];
    int tx = threadIdx.x, ty = threadIdx.y;
    int bx = blockIdx.x * 32, by = blockIdx.y * 32;
    #pragma unroll
    for (int j = 0; j < 32; j += 8)
        t[ty + j][tx] = in[(size_t)(by + ty + j) * Cc + bx + tx];
    __syncthreads();
    #pragma unroll
    for (int j = 0; j < 32; j += 8)
        out[(size_t)(bx + ty + j) * R + by + tx] = t[tx][ty + j];
}

// ---------------------------------------------------------------------------
// LayerNorm: one block per row of 2048
// ---------------------------------------------------------------------------
__global__ __launch_bounds__(256) void ln_k(const float* __restrict__ x,
                                            const float* __restrict__ g,
                                            const float* __restrict__ b,
                                            float* __restrict__ out)
{
    size_t row = blockIdx.x;
    const float4* xr = (const float4*)(x + row * (size_t)C_);
    int tid = threadIdx.x;
    float4 v0 = xr[tid];
    float4 v1 = xr[tid + 256];
    float s  = v0.x + v0.y + v0.z + v0.w + v1.x + v1.y + v1.z + v1.w;
    float s2 = v0.x*v0.x + v0.y*v0.y + v0.z*v0.z + v0.w*v0.w
             + v1.x*v1.x + v1.y*v1.y + v1.z*v1.z + v1.w*v1.w;
    #pragma unroll
    for (int o = 16; o > 0; o >>= 1) {
        s  += __shfl_xor_sync(0xffffffffu, s,  o);
        s2 += __shfl_xor_sync(0xffffffffu, s2, o);
    }
    __shared__ float ssum[8], ssq[8];
    __shared__ float mu_s, inv_s;
    int wid = tid >> 5, lane = tid & 31;
    if (lane == 0) { ssum[wid] = s; ssq[wid] = s2; }
    __syncthreads();
    if (tid == 0) {
        float S = 0.f, S2 = 0.f;
        #pragma unroll
        for (int i = 0; i < 8; ++i) { S += ssum[i]; S2 += ssq[i]; }
        float mu  = S * (1.f / (float)C_);
        float var = S2 * (1.f / (float)C_) - mu * mu;
        mu_s  = mu;
        inv_s = rsqrtf(var + 1e-5f);
    }
    __syncthreads();
    float mu = mu_s, inv = inv_s;
    const float4* g4 = (const float4*)g;
    const float4* b4 = (const float4*)b;
    float4* o4 = (float4*)(out + row * (size_t)C_);
    {
        float4 gg = g4[tid], bb = b4[tid], r;
        r.x = (v0.x - mu) * inv * gg.x + bb.x;
        r.y = (v0.y - mu) * inv * gg.y + bb.y;
        r.z = (v0.z - mu) * inv * gg.z + bb.z;
        r.w = (v0.w - mu) * inv * gg.w + bb.w;
        o4[tid] = r;
    }
    {
        float4 gg = g4[tid + 256], bb = b4[tid + 256], r;
        r.x = (v1.x - mu) * inv * gg.x + bb.x;
        r.y = (v1.y - mu) * inv * gg.y + bb.y;
        r.z = (v1.z - mu) * inv * gg.z + bb.z;
        r.w = (v1.w - mu) * inv * gg.w + bb.w;
        o4[tid + 256] = r;
    }
}

// ---------------------------------------------------------------------------
// tf32 mma.sync GEMM: C[M,N] = A[M,K] @ BT[N,K]^T + bias (+gelu|+residual)
// CTA tile 128x128, K-tile 32, 8 warps in 4(m)x2(n), warp tile 32x64.
// m16n8k8 tf32 fragments (PTX ISA spec):
//   A: a0=(g,t) a1=(g+8,t) a2=(g,t+4) a3=(g+8,t+4)
//   B: b0=(k=t,n=g) b1=(k=t+4,n=g)
//   C: c0=(g,2t) c1=(g,2t+1) c2=(g+8,2t) c3=(g+8,2t+1)
// Scalar LDS with SSTRIDE=36: lane bank = (4g+t+k0) mod 32 -> conflict-free.
// ---------------------------------------------------------------------------
#define EPI_NONE 0
#define EPI_GELU 1
#define EPI_RES  2

#define SSTRIDE 36                 // floats per smem row
#define TILE_FLOATS (128 * SSTRIDE)           // 4608
#define BUF_FLOATS  (2 * TILE_FLOATS)         // A + B per buffer
#define GEMM_SMEM   (2 * BUF_FLOATS * 4)      // 73728 bytes

__device__ __forceinline__ float fast_gelu(float v)
{
    float z = 0.79788456080286536f * (v + 0.044715f * v * v * v);
    float e = __expf(2.f * z);
    float th = 1.f - 2.f / (e + 1.f);
    return 0.5f * v * (1.f + th);
}

__device__ __forceinline__ uint32_t f2tf32(float f)
{
    uint32_t u;
    asm("cvt.rna.tf32.f32 %0, %1;" : "=r"(u) : "f"(f));
    return u;
}

__device__ __forceinline__ void mma_tf32(float* c, const uint32_t* a,
                                         const uint32_t* b)
{
    asm volatile(
        "mma.sync.aligned.m16n8k8.row.col.f32.tf32.tf32.f32 "
        "{%0,%1,%2,%3}, {%4,%5,%6,%7}, {%8,%9}, {%0,%1,%2,%3};"
        : "+f"(c[0]), "+f"(c[1]), "+f"(c[2]), "+f"(c[3])
        : "r"(a[0]), "r"(a[1]), "r"(a[2]), "r"(a[3]), "r"(b[0]), "r"(b[1]));
}

template<int EPI>
__global__ __launch_bounds__(256) void mma_gemm(
    int M, int N, int K,
    const float* __restrict__ A, const float* __restrict__ BT,
    const float* __restrict__ bias, const float* __restrict__ R,
    float* __restrict__ C)
{
    extern __shared__ uint32_t smu[];
    int tid  = threadIdx.x;
    int wid  = tid >> 5, lane = tid & 31;
    int gq   = lane >> 2, tq = lane & 3;       // group / thread-in-group
    int wm   = wid & 3, wn = wid >> 2;         // warp grid 4 x 2
    int m0   = wm * 32, n0 = wn * 64;
    size_t rowBase = (size_t)blockIdx.y * 128;
    size_t colBase = (size_t)blockIdx.x * 128;

    const float* Ab = A  + rowBase * K;
    const float* Bb = BT + colBase * K;

    float acc[2][8][4];
    #pragma unroll
    for (int mf = 0; mf < 2; ++mf)
        #pragma unroll
        for (int nf = 0; nf < 8; ++nf)
            #pragma unroll
            for (int u = 0; u < 4; ++u) acc[mf][nf][u] = 0.f;

    int nk = K >> 5;
    float4 av[4], bv[4];
    #pragma unroll
    for (int it = 0; it < 4; ++it) {
        int i   = tid + it * 256;
        int row = i >> 3;
        int kq  = (i & 7) << 2;
        av[it] = *(const float4*)(Ab + (size_t)row * K + kq);
        bv[it] = *(const float4*)(Bb + (size_t)row * K + kq);
    }

    for (int t = 0; t < nk; ++t) {
        int buf = t & 1;
        uint32_t* as_ = smu + buf * BUF_FLOATS;
        uint32_t* bs_ = as_ + TILE_FLOATS;
        #pragma unroll
        for (int it = 0; it < 4; ++it) {
            int i   = tid + it * 256;
            int row = i >> 3;
            int kq  = (i & 7) << 2;
            uint32_t* ap = as_ + row * SSTRIDE + kq;
            uint32_t* bp = bs_ + row * SSTRIDE + kq;
            ap[0] = f2tf32(av[it].x); ap[1] = f2tf32(av[it].y);
            ap[2] = f2tf32(av[it].z); ap[3] = f2tf32(av[it].w);
            bp[0] = f2tf32(bv[it].x); bp[1] = f2tf32(bv[it].y);
            bp[2] = f2tf32(bv[it].z); bp[3] = f2tf32(bv[it].w);
        }
        __syncthreads();
        if (t + 1 < nk) {
            #pragma unroll
            for (int it = 0; it < 4; ++it) {
                int i   = tid + it * 256;
                int row = i >> 3;
                int kq  = (i & 7) << 2;
                av[it] = *(const float4*)(Ab + (size_t)row * K + (t + 1) * 32 + kq);
                bv[it] = *(const float4*)(Bb + (size_t)row * K + (t + 1) * 32 + kq);
            }
        }
        const uint32_t* aw = as_ + (m0 + gq) * SSTRIDE + tq;
        const uint32_t* bw = bs_ + (n0 + gq) * SSTRIDE + tq;
        #pragma unroll
        for (int ks = 0; ks < 4; ++ks) {
            int k0 = ks * 8;
            uint32_t af[2][4];
            #pragma unroll
            for (int mf = 0; mf < 2; ++mf) {
                const uint32_t* p = aw + mf * 16 * SSTRIDE + k0;
                af[mf][0] = p[0];                    // (g,    t)
                af[mf][1] = p[8 * SSTRIDE];          // (g+8,  t)
                af[mf][2] = p[4];                    // (g,    t+4)
                af[mf][3] = p[8 * SSTRIDE + 4];      // (g+8,  t+4)
            }
            uint32_t bf[8][2];
            #pragma unroll
            for (int nf = 0; nf < 8; ++nf) {
                const uint32_t* p = bw + nf * 8 * SSTRIDE + k0;
                bf[nf][0] = p[0];                    // (k=t,   n=g)
                bf[nf][1] = p[4];                    // (k=t+4, n=g)
            }
            #pragma unroll
            for (int mf = 0; mf < 2; ++mf)
                #pragma unroll
                for (int nf = 0; nf < 8; ++nf)
                    mma_tf32(acc[mf][nf], af[mf], bf[nf]);
        }
        __syncthreads();
    }

    // Epilogue: c0(g,2t) c1(g,2t+1) c2(g+8,2t) c3(g+8,2t+1)
    #pragma unroll
    for (int mf = 0; mf < 2; ++mf) {
        #pragma unroll
        for (int part = 0; part < 2; ++part) {
            size_t row = rowBase + m0 + mf * 16 + gq + part * 8;
            #pragma unroll
            for (int nf = 0; nf < 8; ++nf) {
                size_t col = colBase + n0 + nf * 8 + 2 * tq;
                float v0 = acc[mf][nf][part * 2 + 0];
                float v1 = acc[mf][nf][part * 2 + 1];
                float2 bb = *(const float2*)(bias + col);
                v0 += bb.x; v1 += bb.y;
                if (EPI == EPI_GELU) { v0 = fast_gelu(v0); v1 = fast_gelu(v1); }
                if (EPI == EPI_RES) {
                    float2 rv = *(const float2*)(R + row * N + col);
                    v0 += rv.x; v1 += rv.y;
                }
                *(float2*)(C + row * N + col) = make_float2(v0, v1);
            }
        }
    }
}

// ---------------------------------------------------------------------------
// Causal flash attention (fp32 SIMT). Grid: (32, 64). Block: 128 threads.
// ---------------------------------------------------------------------------
#define ATTN_SMEM ((64 * 132 + 2 * 64 * 128) * 4)

__global__ __launch_bounds__(128) void attn_k(const float* __restrict__ qkv,
                                              float* __restrict__ y)
{
    extern __shared__ float smf[];
    float (*qs)[132] = (float(*)[132])smf;
    float (*ks)[128] = (float(*)[128])(smf + 64 * 132);
    float (*vs)[128] = (float(*)[128])(smf + 64 * 132 + 64 * 128);

    int qt = blockIdx.x;
    int bh = blockIdx.y;
    int b  = bh >> 4;
    int h  = bh & 15;
    int tid = threadIdx.x;
    int r    = tid >> 1;
    int col0 = (tid & 1) * 64;
    const float scale = 0.08838834764831845f;

    const float* base = qkv + (size_t)b * T_ * C3_ + (size_t)h * HD_;
    int q0 = qt * 64;

    for (int i = tid; i < 64 * 32; i += 128) {
        int rr = i >> 5, c4 = (i & 31) << 2;
        *(float4*)&qs[rr][c4] =
            *(const float4*)(base + (size_t)(q0 + rr) * C3_ + c4);
    }

    float o[64];
    #pragma unroll
    for (int d = 0; d < 64; ++d) o[d] = 0.f;
    float m = -1e30f, l = 0.f;

    for (int kt = 0; kt <= qt; ++kt) {
        int k0 = kt * 64;
        __syncthreads();
        for (int i = tid; i < 64 * 32; i += 128) {
            int rr = i >> 5, c4 = (i & 31) << 2;
            *(float4*)&ks[rr][c4] =
                *(const float4*)(base + C_ + (size_t)(k0 + rr) * C3_ + c4);
            *(float4*)&vs[rr][c4] =
                *(const float4*)(base + 2 * C_ + (size_t)(k0 + rr) * C3_ + c4);
        }
        __syncthreads();

        #pragma unroll 1
        for (int sub = 0; sub < 2; ++sub) {
            int j0 = sub * 32;
            float s[32];
            #pragma unroll
            for (int j = 0; j < 32; ++j) s[j] = 0.f;

            #pragma unroll 1
            for (int c = 0; c < 64; c += 16) {
                float qr[16];
                #pragma unroll
                for (int u = 0; u < 16; u += 4)
                    *(float4*)&qr[u] = *(float4*)&qs[r][col0 + c + u];
                #pragma unroll
                for (int j = 0; j < 32; ++j) {
                    const float* kr = &ks[j0 + j][col0 + c];
                    float4 k1 = *(const float4*)(kr);
                    float4 k2 = *(const float4*)(kr + 4);
                    float4 k3 = *(const float4*)(kr + 8);
                    float4 k4 = *(const float4*)(kr + 12);
                    s[j] += qr[0]  * k1.x + qr[1]  * k1.y + qr[2]  * k1.z + qr[3]  * k1.w
                          + qr[4]  * k2.x + qr[5]  * k2.y + qr[6]  * k2.z + qr[7]  * k2.w
                          + qr[8]  * k3.x + qr[9]  * k3.y + qr[10] * k3.z + qr[11] * k3.w
                          + qr[12] * k4.x + qr[13] * k4.y + qr[14] * k4.z + qr[15] * k4.w;
                }
            }
            #pragma unroll
            for (int j = 0; j < 32; ++j)
                s[j] = scale * (s[j] + __shfl_xor_sync(0xffffffffu, s[j], 1));

            if (kt == qt) {
                #pragma unroll
                for (int j = 0; j < 32; ++j)
                    if (j0 + j > r) s[j] = -1e30f;
            }

            float mnew = m;
            #pragma unroll
            for (int j = 0; j < 32; ++j) mnew = fmaxf(mnew, s[j]);
            float corr = __expf(m - mnew);
            l *= corr;
            #pragma unroll
            for (int d = 0; d < 64; ++d) o[d] *= corr;
            float ls = 0.f;
            #pragma unroll
            for (int j = 0; j < 32; ++j) {
                float p = __expf(s[j] - mnew);
                s[j] = p;
                ls += p;
            }
            l += ls;
            m = mnew;

            #pragma unroll
            for (int j = 0; j < 32; ++j) {
                float pj = s[j];
                const float* vr = &vs[j0 + j][col0];
                #pragma unroll
                for (int d = 0; d < 64; d += 4) {
                    float4 vv = *(const float4*)(vr + d);
                    o[d]     += pj * vv.x;
                    o[d + 1] += pj * vv.y;
                    o[d + 2] += pj * vv.z;
                    o[d + 3] += pj * vv.w;
                }
            }
        }
    }

    float inv = 1.f / l;
    float* yr = y + (size_t)(b * T_ + q0 + r) * C_ + h * HD_ + col0;
    #pragma unroll
    for (int d = 0; d < 64; d += 4) {
        *(float4*)(yr + d) = make_float4(o[d] * inv, o[d + 1] * inv,
                                         o[d + 2] * inv, o[d + 3] * inv);
    }
}

// ---------------------------------------------------------------------------
// Launch
// ---------------------------------------------------------------------------
extern "C" void kernel_launch(void* const* d_in, const int* in_sizes, int n_in,
                              void* d_out, int out_size)
{
    const float* x         = (const float*)d_in[0];
    const float* ln1_g     = (const float*)d_in[1];
    const float* ln1_b     = (const float*)d_in[2];
    const float* w_attn    = (const float*)d_in[3];
    const float* b_attn    = (const float*)d_in[4];
    const float* w_proj    = (const float*)d_in[5];
    const float* b_proj    = (const float*)d_in[6];
    const float* ln2_g     = (const float*)d_in[7];
    const float* ln2_b     = (const float*)d_in[8];
    const float* w_fc      = (const float*)d_in[9];
    const float* b_fc      = (const float*)d_in[10];
    const float* w_fc_proj = (const float*)d_in[11];
    const float* b_fc_proj = (const float*)d_in[12];
    float* out = (float*)d_out;

    float *h, *qkv, *y, *fc, *wt_attn, *wt_proj, *wt_fc, *wt_fcproj;
    cudaGetSymbolAddress((void**)&h,         g_h);
    cudaGetSymbolAddress((void**)&qkv,       g_qkv);
    cudaGetSymbolAddress((void**)&y,         g_y);
    cudaGetSymbolAddress((void**)&fc,        g_fc);
    cudaGetSymbolAddress((void**)&wt_attn,   g_wt_attn);
    cudaGetSymbolAddress((void**)&wt_proj,   g_wt_proj);
    cudaGetSymbolAddress((void**)&wt_fc,     g_wt_fc);
    cudaGetSymbolAddress((void**)&wt_fcproj, g_wt_fcproj);

    cudaFuncSetAttribute(attn_k, cudaFuncAttributeMaxDynamicSharedMemorySize,
                         ATTN_SMEM);
    cudaFuncSetAttribute(mma_gemm<EPI_NONE>,
                         cudaFuncAttributeMaxDynamicSharedMemorySize, GEMM_SMEM);
    cudaFuncSetAttribute(mma_gemm<EPI_GELU>,
                         cudaFuncAttributeMaxDynamicSharedMemorySize, GEMM_SMEM);
    cudaFuncSetAttribute(mma_gemm<EPI_RES>,
                         cudaFuncAttributeMaxDynamicSharedMemorySize, GEMM_SMEM);

    dim3 tb(32, 8);
    // 0) weight transposes (weights treated as ordinary per-launch inputs)
    transpose_k<<<dim3(C3_ / 32, C_ / 32), tb>>>(w_attn, wt_attn, C_, C3_);
    transpose_k<<<dim3(C_ / 32, C_ / 32),  tb>>>(w_proj, wt_proj, C_, C_);
    transpose_k<<<dim3(C4_ / 32, C_ / 32), tb>>>(w_fc, wt_fc, C_, C4_);
    transpose_k<<<dim3(C_ / 32, C4_ / 32), tb>>>(w_fc_proj, wt_fcproj, C4_, C_);

    // 1) h = LN1(x)
    ln_k<<<BT_, 256>>>(x, ln1_g, ln1_b, h);
    // 2) qkv = h @ w_attn + b_attn
    mma_gemm<EPI_NONE><<<dim3(C3_ / 128, BT_ / 128), 256, GEMM_SMEM>>>(
        BT_, C3_, C_, h, wt_attn, b_attn, nullptr, qkv);
    // 3) y = causal_attention(qkv)
    attn_k<<<dim3(T_ / 64, B_ * NH_), 128, ATTN_SMEM>>>(qkv, y);
    // 4) out = x + y @ w_proj + b_proj
    mma_gemm<EPI_RES><<<dim3(C_ / 128, BT_ / 128), 256, GEMM_SMEM>>>(
        BT_, C_, C_, y, wt_proj, b_proj, x, out);
    // 5) h = LN2(out)
    ln_k<<<BT_, 256>>>(out, ln2_g, ln2_b, h);
    // 6) fc = gelu(h @ w_fc + b_fc)
    mma_gemm<EPI_GELU><<<dim3(C4_ / 128, BT_ / 128), 256, GEMM_SMEM>>>(
        BT_, C4_, C_, h, wt_fc, b_fc, nullptr, fc);
    // 7) out = out + fc @ w_fc_proj + b_fc_proj
    mma_gemm<EPI_RES><<<dim3(C_ / 128, BT_ / 128), 256, GEMM_SMEM>>>(
        BT_, C_, C4_, fc, wt_fcproj, b_fc_proj, out, out);
}

// round 8
// speedup vs baseline: 1.9306x; 1.1321x over previous
#include <cuda_runtime.h>
#include <cstdint>
#include <cstddef>

// ---------------------------------------------------------------------------
// Problem dims (fixed): B=4, T=2048, C=2048, H=16, HD=128
// ---------------------------------------------------------------------------
#define B_  4
#define T_  2048
#define C_  2048
#define BT_ (B_ * T_)          // 8192
#define C3_ (3 * C_)           // 6144
#define C4_ (4 * C_)           // 8192
#define NH_ 16
#define HD_ 128

// ---------------------------------------------------------------------------
// Scratch (device globals: allocation-free rule)
// ---------------------------------------------------------------------------
__device__ float g_h[(size_t)BT_ * C_];       // LN output
__device__ float g_qkv[(size_t)BT_ * C3_];    // QKV
__device__ float g_y[(size_t)BT_ * C_];       // attention output
__device__ float g_fc[(size_t)BT_ * C4_];     // gelu(fc)
__device__ float g_wt_attn[(size_t)C3_ * C_];    // w_attn^T   [6144,2048]
__device__ float g_wt_proj[(size_t)C_ * C_];     // w_proj^T   [2048,2048]
__device__ float g_wt_fc[(size_t)C4_ * C_];      // w_fc^T     [8192,2048]
__device__ float g_wt_fcproj[(size_t)C_ * C4_];  // w_fc_proj^T[2048,8192]

// ---------------------------------------------------------------------------
// cp.async helpers
// ---------------------------------------------------------------------------
__device__ __forceinline__ uint32_t smem_u32(const void* p)
{
    return (uint32_t)__cvta_generic_to_shared(p);
}
#define CP_ASYNC16(dst, src) \
    asm volatile("cp.async.cg.shared.global [%0], [%1], 16;" \
                 :: "r"(dst), "l"(src) : "memory")
#define CP_COMMIT() asm volatile("cp.async.commit_group;" ::: "memory")
#define CP_WAIT(n)  asm volatile("cp.async.wait_group %0;" :: "n"(n) : "memory")

// ---------------------------------------------------------------------------
// Weight transpose: in[R][Cc] -> out[Cc][R]   (dims multiples of 32)
// ---------------------------------------------------------------------------
__global__ __launch_bounds__(256) void transpose_k(const float* __restrict__ in,
                                                   float* __restrict__ out,
                                                   int R, int Cc)
{
    __shared__ float t[32][33];
    int tx = threadIdx.x, ty = threadIdx.y;
    int bx = blockIdx.x * 32, by = blockIdx.y * 32;
    #pragma unroll
    for (int j = 0; j < 32; j += 8)
        t[ty + j][tx] = in[(size_t)(by + ty + j) * Cc + bx + tx];
    __syncthreads();
    #pragma unroll
    for (int j = 0; j < 32; j += 8)
        out[(size_t)(bx + ty + j) * R + by + tx] = t[tx][ty + j];
}

// ---------------------------------------------------------------------------
// LayerNorm: one block per row of 2048
// ---------------------------------------------------------------------------
__global__ __launch_bounds__(256) void ln_k(const float* __restrict__ x,
                                            const float* __restrict__ g,
                                            const float* __restrict__ b,
                                            float* __restrict__ out)
{
    size_t row = blockIdx.x;
    const float4* xr = (const float4*)(x + row * (size_t)C_);
    int tid = threadIdx.x;
    float4 v0 = xr[tid];
    float4 v1 = xr[tid + 256];
    float s  = v0.x + v0.y + v0.z + v0.w + v1.x + v1.y + v1.z + v1.w;
    float s2 = v0.x*v0.x + v0.y*v0.y + v0.z*v0.z + v0.w*v0.w
             + v1.x*v1.x + v1.y*v1.y + v1.z*v1.z + v1.w*v1.w;
    #pragma unroll
    for (int o = 16; o > 0; o >>= 1) {
        s  += __shfl_xor_sync(0xffffffffu, s,  o);
        s2 += __shfl_xor_sync(0xffffffffu, s2, o);
    }
    __shared__ float ssum[8], ssq[8];
    __shared__ float mu_s, inv_s;
    int wid = tid >> 5, lane = tid & 31;
    if (lane == 0) { ssum[wid] = s; ssq[wid] = s2; }
    __syncthreads();
    if (tid == 0) {
        float S = 0.f, S2 = 0.f;
        #pragma unroll
        for (int i = 0; i < 8; ++i) { S += ssum[i]; S2 += ssq[i]; }
        float mu  = S * (1.f / (float)C_);
        float var = S2 * (1.f / (float)C_) - mu * mu;
        mu_s  = mu;
        inv_s = rsqrtf(var + 1e-5f);
    }
    __syncthreads();
    float mu = mu_s, inv = inv_s;
    const float4* g4 = (const float4*)g;
    const float4* b4 = (const float4*)b;
    float4* o4 = (float4*)(out + row * (size_t)C_);
    {
        float4 gg = g4[tid], bb = b4[tid], r;
        r.x = (v0.x - mu) * inv * gg.x + bb.x;
        r.y = (v0.y - mu) * inv * gg.y + bb.y;
        r.z = (v0.z - mu) * inv * gg.z + bb.z;
        r.w = (v0.w - mu) * inv * gg.w + bb.w;
        o4[tid] = r;
    }
    {
        float4 gg = g4[tid + 256], bb = b4[tid + 256], r;
        r.x = (v1.x - mu) * inv * gg.x + bb.x;
        r.y = (v1.y - mu) * inv * gg.y + bb.y;
        r.z = (v1.z - mu) * inv * gg.z + bb.z;
        r.w = (v1.w - mu) * inv * gg.w + bb.w;
        o4[tid + 256] = r;
    }
}

// ---------------------------------------------------------------------------
// tf32 mma.sync GEMM: C[M,N] = A[M,K] @ BT[N,K]^T + bias (+gelu|+residual)
// CTA tile 256x128, K-tile 32, 8 warps in 4(m)x2(n), warp tile 64x64.
// cp.async 16B fills (raw f32 bits as tf32 -- HW truncates), 2-stage pipe.
// m16n8k8 tf32 fragments (PTX ISA spec):
//   A: a0=(g,t) a1=(g+8,t) a2=(g,t+4) a3=(g+8,t+4)
//   B: b0=(k=t,n=g) b1=(k=t+4,n=g)
//   C: c0=(g,2t) c1=(g,2t+1) c2=(g+8,2t) c3=(g+8,2t+1)
// Scalar LDS with stride 36: lane bank = (4g+t+const) mod 32 -> conflict-free.
// ---------------------------------------------------------------------------
#define EPI_NONE 0
#define EPI_GELU 1
#define EPI_RES  2

#define CTA_M 256
#define CTA_N 128
#define SSTRIDE 36
#define A_TILE_FLOATS (CTA_M * SSTRIDE)            // 9216
#define B_TILE_FLOATS (CTA_N * SSTRIDE)            // 4608
#define BUF_FLOATS    (A_TILE_FLOATS + B_TILE_FLOATS)
#define GEMM_SMEM     (2 * BUF_FLOATS * 4)         // 110592 bytes

__device__ __forceinline__ float fast_gelu(float v)
{
    float z = 0.79788456080286536f * (v + 0.044715f * v * v * v);
    float e = __expf(2.f * z);
    float th = 1.f - 2.f / (e + 1.f);
    return 0.5f * v * (1.f + th);
}

__device__ __forceinline__ void mma_tf32(float* c, const uint32_t* a,
                                         const uint32_t* b)
{
    asm volatile(
        "mma.sync.aligned.m16n8k8.row.col.f32.tf32.tf32.f32 "
        "{%0,%1,%2,%3}, {%4,%5,%6,%7}, {%8,%9}, {%0,%1,%2,%3};"
        : "+f"(c[0]), "+f"(c[1]), "+f"(c[2]), "+f"(c[3])
        : "r"(a[0]), "r"(a[1]), "r"(a[2]), "r"(a[3]), "r"(b[0]), "r"(b[1]));
}

template<int EPI>
__global__ __launch_bounds__(256, 1) void mma_gemm(
    int M, int N, int K,
    const float* __restrict__ A, const float* __restrict__ BT,
    const float* __restrict__ bias, const float* __restrict__ R,
    float* __restrict__ C)
{
    extern __shared__ float smf_g[];
    uint32_t sbase = smem_u32(smf_g);
    int tid  = threadIdx.x;
    int wid  = tid >> 5, lane = tid & 31;
    int gq   = lane >> 2, tq = lane & 3;
    int wm   = wid & 3, wn = wid >> 2;         // warp grid 4(m) x 2(n)
    int m0   = wm * 64, n0 = wn * 64;
    size_t rowBase = (size_t)blockIdx.y * CTA_M;
    size_t colBase = (size_t)blockIdx.x * CTA_N;

    const float* Ab = A  + rowBase * K;
    const float* Bb = BT + colBase * K;
    int fRow = tid >> 3;                       // 0..31
    int fK   = (tid & 7) << 2;                 // 0,4,...,28

    float acc[4][8][4];
    #pragma unroll
    for (int mf = 0; mf < 4; ++mf)
        #pragma unroll
        for (int nf = 0; nf < 8; ++nf)
            #pragma unroll
            for (int u = 0; u < 4; ++u) acc[mf][nf][u] = 0.f;

    int nk = K >> 5;

    // fill buffer `buf` with K-chunk t
    auto fill = [&](int buf, int t) {
        uint32_t sa = sbase + (uint32_t)(buf * BUF_FLOATS * 4);
        uint32_t sb = sa + A_TILE_FLOATS * 4;
        #pragma unroll
        for (int it = 0; it < 8; ++it) {       // A: 256 rows
            int row = fRow + it * 32;
            CP_ASYNC16(sa + (uint32_t)((row * SSTRIDE + fK) * 4),
                       Ab + (size_t)row * K + t * 32 + fK);
        }
        #pragma unroll
        for (int it = 0; it < 4; ++it) {       // B: 128 rows
            int row = fRow + it * 32;
            CP_ASYNC16(sb + (uint32_t)((row * SSTRIDE + fK) * 4),
                       Bb + (size_t)row * K + t * 32 + fK);
        }
        CP_COMMIT();
    };

    fill(0, 0);
    for (int t = 0; t < nk; ++t) {
        if (t + 1 < nk) { fill((t + 1) & 1, t + 1); CP_WAIT(1); }
        else            { CP_WAIT(0); }
        __syncthreads();

        const float* smA = smf_g + (t & 1) * BUF_FLOATS;
        const float* smB = smA + A_TILE_FLOATS;
        const uint32_t* aw = (const uint32_t*)smA + (m0 + gq) * SSTRIDE + tq;
        const uint32_t* bw = (const uint32_t*)smB + (n0 + gq) * SSTRIDE + tq;

        #pragma unroll
        for (int ks = 0; ks < 4; ++ks) {
            int k0 = ks * 8;
            uint32_t af[4][4];
            #pragma unroll
            for (int mf = 0; mf < 4; ++mf) {
                const uint32_t* p = aw + mf * 16 * SSTRIDE + k0;
                af[mf][0] = p[0];                    // (g,    t)
                af[mf][1] = p[8 * SSTRIDE];          // (g+8,  t)
                af[mf][2] = p[4];                    // (g,    t+4)
                af[mf][3] = p[8 * SSTRIDE + 4];      // (g+8,  t+4)
            }
            uint32_t bf[8][2];
            #pragma unroll
            for (int nf = 0; nf < 8; ++nf) {
                const uint32_t* p = bw + nf * 8 * SSTRIDE + k0;
                bf[nf][0] = p[0];                    // (k=t,   n=g)
                bf[nf][1] = p[4];                    // (k=t+4, n=g)
            }
            #pragma unroll
            for (int mf = 0; mf < 4; ++mf)
                #pragma unroll
                for (int nf = 0; nf < 8; ++nf)
                    mma_tf32(acc[mf][nf], af[mf], bf[nf]);
        }
        __syncthreads();
    }

    // Epilogue: c0(g,2t) c1(g,2t+1) c2(g+8,2t) c3(g+8,2t+1)
    #pragma unroll
    for (int mf = 0; mf < 4; ++mf) {
        #pragma unroll
        for (int part = 0; part < 2; ++part) {
            size_t row = rowBase + m0 + mf * 16 + gq + part * 8;
            #pragma unroll
            for (int nf = 0; nf < 8; ++nf) {
                size_t col = colBase + n0 + nf * 8 + 2 * tq;
                float v0 = acc[mf][nf][part * 2 + 0];
                float v1 = acc[mf][nf][part * 2 + 1];
                float2 bb = *(const float2*)(bias + col);
                v0 += bb.x; v1 += bb.y;
                if (EPI == EPI_GELU) { v0 = fast_gelu(v0); v1 = fast_gelu(v1); }
                if (EPI == EPI_RES) {
                    float2 rv = *(const float2*)(R + row * N + col);
                    v0 += rv.x; v1 += rv.y;
                }
                *(float2*)(C + row * N + col) = make_float2(v0, v1);
            }
        }
    }
}

// ---------------------------------------------------------------------------
// Causal flash attention (fp32 SIMT). Grid: (32, 64). Block: 128 threads.
// ---------------------------------------------------------------------------
#define ATTN_SMEM ((64 * 132 + 2 * 64 * 128) * 4)

__global__ __launch_bounds__(128) void attn_k(const float* __restrict__ qkv,
                                              float* __restrict__ y)
{
    extern __shared__ float smf[];
    float (*qs)[132] = (float(*)[132])smf;
    float (*ks)[128] = (float(*)[128])(smf + 64 * 132);
    float (*vs)[128] = (float(*)[128])(smf + 64 * 132 + 64 * 128);

    int qt = blockIdx.x;
    int bh = blockIdx.y;
    int b  = bh >> 4;
    int h  = bh & 15;
    int tid = threadIdx.x;
    int r    = tid >> 1;
    int col0 = (tid & 1) * 64;
    const float scale = 0.08838834764831845f;

    const float* base = qkv + (size_t)b * T_ * C3_ + (size_t)h * HD_;
    int q0 = qt * 64;

    for (int i = tid; i < 64 * 32; i += 128) {
        int rr = i >> 5, c4 = (i & 31) << 2;
        *(float4*)&qs[rr][c4] =
            *(const float4*)(base + (size_t)(q0 + rr) * C3_ + c4);
    }

    float o[64];
    #pragma unroll
    for (int d = 0; d < 64; ++d) o[d] = 0.f;
    float m = -1e30f, l = 0.f;

    for (int kt = 0; kt <= qt; ++kt) {
        int k0 = kt * 64;
        __syncthreads();
        for (int i = tid; i < 64 * 32; i += 128) {
            int rr = i >> 5, c4 = (i & 31) << 2;
            *(float4*)&ks[rr][c4] =
                *(const float4*)(base + C_ + (size_t)(k0 + rr) * C3_ + c4);
            *(float4*)&vs[rr][c4] =
                *(const float4*)(base + 2 * C_ + (size_t)(k0 + rr) * C3_ + c4);
        }
        __syncthreads();

        #pragma unroll 1
        for (int sub = 0; sub < 2; ++sub) {
            int j0 = sub * 32;
            float s[32];
            #pragma unroll
            for (int j = 0; j < 32; ++j) s[j] = 0.f;

            #pragma unroll 1
            for (int c = 0; c < 64; c += 16) {
                float qr[16];
                #pragma unroll
                for (int u = 0; u < 16; u += 4)
                    *(float4*)&qr[u] = *(float4*)&qs[r][col0 + c + u];
                #pragma unroll
                for (int j = 0; j < 32; ++j) {
                    const float* kr = &ks[j0 + j][col0 + c];
                    float4 k1 = *(const float4*)(kr);
                    float4 k2 = *(const float4*)(kr + 4);
                    float4 k3 = *(const float4*)(kr + 8);
                    float4 k4 = *(const float4*)(kr + 12);
                    s[j] += qr[0]  * k1.x + qr[1]  * k1.y + qr[2]  * k1.z + qr[3]  * k1.w
                          + qr[4]  * k2.x + qr[5]  * k2.y + qr[6]  * k2.z + qr[7]  * k2.w
                          + qr[8]  * k3.x + qr[9]  * k3.y + qr[10] * k3.z + qr[11] * k3.w
                          + qr[12] * k4.x + qr[13] * k4.y + qr[14] * k4.z + qr[15] * k4.w;
                }
            }
            #pragma unroll
            for (int j = 0; j < 32; ++j)
                s[j] = scale * (s[j] + __shfl_xor_sync(0xffffffffu, s[j], 1));

            if (kt == qt) {
                #pragma unroll
                for (int j = 0; j < 32; ++j)
                    if (j0 + j > r) s[j] = -1e30f;
            }

            float mnew = m;
            #pragma unroll
            for (int j = 0; j < 32; ++j) mnew = fmaxf(mnew, s[j]);
            float corr = __expf(m - mnew);
            l *= corr;
            #pragma unroll
            for (int d = 0; d < 64; ++d) o[d] *= corr;
            float ls = 0.f;
            #pragma unroll
            for (int j = 0; j < 32; ++j) {
                float p = __expf(s[j] - mnew);
                s[j] = p;
                ls += p;
            }
            l += ls;
            m = mnew;

            #pragma unroll
            for (int j = 0; j < 32; ++j) {
                float pj = s[j];
                const float* vr = &vs[j0 + j][col0];
                #pragma unroll
                for (int d = 0; d < 64; d += 4) {
                    float4 vv = *(const float4*)(vr + d);
                    o[d]     += pj * vv.x;
                    o[d + 1] += pj * vv.y;
                    o[d + 2] += pj * vv.z;
                    o[d + 3] += pj * vv.w;
                }
            }
        }
    }

    float inv = 1.f / l;
    float* yr = y + (size_t)(b * T_ + q0 + r) * C_ + h * HD_ + col0;
    #pragma unroll
    for (int d = 0; d < 64; d += 4) {
        *(float4*)(yr + d) = make_float4(o[d] * inv, o[d + 1] * inv,
                                         o[d + 2] * inv, o[d + 3] * inv);
    }
}

// ---------------------------------------------------------------------------
// Launch
// ---------------------------------------------------------------------------
extern "C" void kernel_launch(void* const* d_in, const int* in_sizes, int n_in,
                              void* d_out, int out_size)
{
    const float* x         = (const float*)d_in[0];
    const float* ln1_g     = (const float*)d_in[1];
    const float* ln1_b     = (const float*)d_in[2];
    const float* w_attn    = (const float*)d_in[3];
    const float* b_attn    = (const float*)d_in[4];
    const float* w_proj    = (const float*)d_in[5];
    const float* b_proj    = (const float*)d_in[6];
    const float* ln2_g     = (const float*)d_in[7];
    const float* ln2_b     = (const float*)d_in[8];
    const float* w_fc      = (const float*)d_in[9];
    const float* b_fc      = (const float*)d_in[10];
    const float* w_fc_proj = (const float*)d_in[11];
    const float* b_fc_proj = (const float*)d_in[12];
    float* out = (float*)d_out;

    float *h, *qkv, *y, *fc, *wt_attn, *wt_proj, *wt_fc, *wt_fcproj;
    cudaGetSymbolAddress((void**)&h,         g_h);
    cudaGetSymbolAddress((void**)&qkv,       g_qkv);
    cudaGetSymbolAddress((void**)&y,         g_y);
    cudaGetSymbolAddress((void**)&fc,        g_fc);
    cudaGetSymbolAddress((void**)&wt_attn,   g_wt_attn);
    cudaGetSymbolAddress((void**)&wt_proj,   g_wt_proj);
    cudaGetSymbolAddress((void**)&wt_fc,     g_wt_fc);
    cudaGetSymbolAddress((void**)&wt_fcproj, g_wt_fcproj);

    cudaFuncSetAttribute(attn_k, cudaFuncAttributeMaxDynamicSharedMemorySize,
                         ATTN_SMEM);
    cudaFuncSetAttribute(mma_gemm<EPI_NONE>,
                         cudaFuncAttributeMaxDynamicSharedMemorySize, GEMM_SMEM);
    cudaFuncSetAttribute(mma_gemm<EPI_GELU>,
                         cudaFuncAttributeMaxDynamicSharedMemorySize, GEMM_SMEM);
    cudaFuncSetAttribute(mma_gemm<EPI_RES>,
                         cudaFuncAttributeMaxDynamicSharedMemorySize, GEMM_SMEM);

    dim3 tb(32, 8);
    // 0) weight transposes (weights treated as ordinary per-launch inputs)
    transpose_k<<<dim3(C3_ / 32, C_ / 32), tb>>>(w_attn, wt_attn, C_, C3_);
    transpose_k<<<dim3(C_ / 32, C_ / 32),  tb>>>(w_proj, wt_proj, C_, C_);
    transpose_k<<<dim3(C4_ / 32, C_ / 32), tb>>>(w_fc, wt_fc, C_, C4_);
    transpose_k<<<dim3(C_ / 32, C4_ / 32), tb>>>(w_fc_proj, wt_fcproj, C4_, C_);

    // 1) h = LN1(x)
    ln_k<<<BT_, 256>>>(x, ln1_g, ln1_b, h);
    // 2) qkv = h @ w_attn + b_attn
    mma_gemm<EPI_NONE><<<dim3(C3_ / CTA_N, BT_ / CTA_M), 256, GEMM_SMEM>>>(
        BT_, C3_, C_, h, wt_attn, b_attn, nullptr, qkv);
    // 3) y = causal_attention(qkv)
    attn_k<<<dim3(T_ / 64, B_ * NH_), 128, ATTN_SMEM>>>(qkv, y);
    // 4) out = x + y @ w_proj + b_proj
    mma_gemm<EPI_RES><<<dim3(C_ / CTA_N, BT_ / CTA_M), 256, GEMM_SMEM>>>(
        BT_, C_, C_, y, wt_proj, b_proj, x, out);
    // 5) h = LN2(out)
    ln_k<<<BT_, 256>>>(out, ln2_g, ln2_b, h);
    // 6) fc = gelu(h @ w_fc + b_fc)
    mma_gemm<EPI_GELU><<<dim3(C4_ / CTA_N, BT_ / CTA_M), 256, GEMM_SMEM>>>(
        BT_, C4_, C_, h, wt_fc, b_fc, nullptr, fc);
    // 7) out = out + fc @ w_fc_proj + b_fc_proj
    mma_gemm<EPI_RES><<<dim3(C_ / CTA_N, BT_ / CTA_M), 256, GEMM_SMEM>>>(
        BT_, C_, C4_, fc, wt_fcproj, b_fc_proj, out, out);
}